// round 1
// baseline (speedup 1.0000x reference)
#include <cuda_runtime.h>
#include <math.h>
#include <stdint.h>

#define NN 50000
#define EE 400000

// ---------------- scratch (device globals; no allocation) ----------------
__device__ float g_x[(size_t)NN * 192];
__device__ float g_xl1[(size_t)NN * 256];
__device__ float g_xr1[(size_t)NN * 256];
__device__ float g_h[(size_t)NN * 256];
__device__ float g_xl2[(size_t)NN * 64];
__device__ float g_xr2[(size_t)NN * 64];
__device__ float g_cs[(size_t)NN * 64];
__device__ int g_deg[NN];
__device__ int g_off[NN + 1];
__device__ int g_cur[NN];
__device__ int g_csr[EE];

// ---------------- CSR build ----------------
__global__ void count_deg_kernel(const int* __restrict__ dst, int e, int* __restrict__ deg) {
    int i = blockIdx.x * blockDim.x + threadIdx.x;
    if (i < e) atomicAdd(&deg[dst[i]], 1);
}

__global__ void scan_offsets_kernel(const int* __restrict__ deg, int* __restrict__ off,
                                    int* __restrict__ cur, int n) {
    __shared__ int s[1024];
    __shared__ int carry;
    int tid = threadIdx.x;
    if (tid == 0) carry = 0;
    __syncthreads();
    for (int base = 0; base < n; base += 1024) {
        int i = base + tid;
        int v = (i < n) ? deg[i] : 0;
        s[tid] = v;
        __syncthreads();
        // Hillis-Steele inclusive scan
        #pragma unroll
        for (int d = 1; d < 1024; d <<= 1) {
            int t = (tid >= d) ? s[tid - d] : 0;
            __syncthreads();
            s[tid] += t;
            __syncthreads();
        }
        int c = carry;
        int incl = s[tid] + c;
        if (i < n) { off[i] = incl - v; cur[i] = incl - v; }
        __syncthreads();
        if (tid == 1023) carry = incl;
        __syncthreads();
    }
    if (tid == 0) off[n] = carry;
}

__global__ void scatter_kernel(const int* __restrict__ src, const int* __restrict__ dst, int e,
                               int* __restrict__ cur, int* __restrict__ csr) {
    int i = blockIdx.x * blockDim.x + threadIdx.x;
    if (i < e) {
        int p = atomicAdd(&cur[dst[i]], 1);
        csr[p] = src[i];
    }
}

// ---------------- feature gather: x = [ts | ent_emb | time_emb] ----------------
__global__ void gather_x_kernel(const float* __restrict__ ts, const int* __restrict__ eidx,
                                const int* __restrict__ tdx, const float* __restrict__ etab,
                                const float* __restrict__ ttab, float* __restrict__ x, int n) {
    int i = blockIdx.x * blockDim.x + threadIdx.x;
    int total = n * 48;  // 192 floats = 48 float4 per row
    if (i >= total) return;
    int row = i / 48;
    int c = i - row * 48;
    float4 v;
    if (c < 16)      v = reinterpret_cast<const float4*>(ts)[(size_t)row * 16 + c];
    else if (c < 32) v = reinterpret_cast<const float4*>(etab)[(size_t)eidx[row] * 16 + (c - 16)];
    else             v = reinterpret_cast<const float4*>(ttab)[(size_t)tdx[row] * 16 + (c - 32)];
    reinterpret_cast<float4*>(x)[(size_t)row * 48 + c] = v;
}

// ---------------- SGEMM: C = A[M,K] @ B[K,N] + bias[N] ----------------
// BM=128, BN=64, BK=16, 256 threads, 8x4 per-thread microtile.
__global__ __launch_bounds__(256) void sgemm_bias_kernel(
    const float* __restrict__ A, const float* __restrict__ B,
    const float* __restrict__ bias, float* __restrict__ C,
    int M, int Nn, int K) {
    __shared__ float As[16][128];
    __shared__ float Bs[16][64];
    int tid = threadIdx.x;
    int tx = tid & 15;
    int ty = tid >> 4;
    int bm = blockIdx.y * 128;
    int bn = blockIdx.x * 64;
    float acc[8][4];
    #pragma unroll
    for (int i = 0; i < 8; i++)
        #pragma unroll
        for (int j = 0; j < 4; j++) acc[i][j] = 0.f;

    for (int k0 = 0; k0 < K; k0 += 16) {
        #pragma unroll
        for (int l = 0; l < 2; l++) {
            int idx = tid + l * 256;
            int r = idx >> 2;
            int c4 = idx & 3;
            int gr = bm + r;
            float4 v = make_float4(0.f, 0.f, 0.f, 0.f);
            if (gr < M) v = *reinterpret_cast<const float4*>(A + (size_t)gr * K + k0 + c4 * 4);
            As[c4 * 4 + 0][r] = v.x;
            As[c4 * 4 + 1][r] = v.y;
            As[c4 * 4 + 2][r] = v.z;
            As[c4 * 4 + 3][r] = v.w;
        }
        {
            int r = tid >> 4;
            int c4 = tid & 15;
            float4 v = *reinterpret_cast<const float4*>(B + (size_t)(k0 + r) * Nn + bn + c4 * 4);
            *reinterpret_cast<float4*>(&Bs[r][c4 * 4]) = v;
        }
        __syncthreads();
        #pragma unroll
        for (int k = 0; k < 16; k++) {
            float4 a0 = *reinterpret_cast<const float4*>(&As[k][ty * 8]);
            float4 a1 = *reinterpret_cast<const float4*>(&As[k][ty * 8 + 4]);
            float4 bv = *reinterpret_cast<const float4*>(&Bs[k][tx * 4]);
            float a[8] = {a0.x, a0.y, a0.z, a0.w, a1.x, a1.y, a1.z, a1.w};
            float b[4] = {bv.x, bv.y, bv.z, bv.w};
            #pragma unroll
            for (int i = 0; i < 8; i++)
                #pragma unroll
                for (int j = 0; j < 4; j++)
                    acc[i][j] = fmaf(a[i], b[j], acc[i][j]);
        }
        __syncthreads();
    }
    float4 bb = *reinterpret_cast<const float4*>(bias + bn + tx * 4);
    int row0 = bm + ty * 8;
    #pragma unroll
    for (int i = 0; i < 8; i++) {
        int r = row0 + i;
        if (r < M) {
            float4 o = make_float4(acc[i][0] + bb.x, acc[i][1] + bb.y,
                                   acc[i][2] + bb.z, acc[i][3] + bb.w);
            *reinterpret_cast<float4*>(C + (size_t)r * Nn + bn + tx * 4) = o;
        }
    }
}

// ---------------- GATv2 aggregation: warp per dst node, online softmax ----------------
// out[dst] = sum_e softmax_e( a . leakyrelu(xl[src]+xr[dst]) ) * xl[src]  (+bias, opt relu)
template <int HEADS, int DIM>
__global__ __launch_bounds__(256) void gat_aggregate(
    const float* __restrict__ xl, const float* __restrict__ xr,
    const float* __restrict__ att, const float* __restrict__ bias,
    const int* __restrict__ off, const int* __restrict__ csr,
    float* __restrict__ out, int n, int do_relu) {
    constexpr int F = HEADS * DIM;
    constexpr int PER = F / 32;      // floats per lane
    constexpr int G = DIM / PER;     // lanes per head
    int gw = (blockIdx.x * blockDim.x + threadIdx.x) >> 5;
    int lane = threadIdx.x & 31;
    if (gw >= n) return;
    int node = gw;

    float xrv[PER], av[PER];
    {
        const float* xrp = xr + (size_t)node * F + lane * PER;
        const float* ap = att + lane * PER;
        #pragma unroll
        for (int j = 0; j < PER; j++) { xrv[j] = xrp[j]; av[j] = ap[j]; }
    }

    int o0 = off[node];
    int deg = off[node + 1] - o0;

    float m = -INFINITY;
    float denom = 0.f;
    float acc[PER];
    #pragma unroll
    for (int j = 0; j < PER; j++) acc[j] = 0.f;

    for (int e = 0; e <= deg; e++) {
        int src = (e == 0) ? node : csr[o0 + e - 1];
        const float* xlp = xl + (size_t)src * F + lane * PER;
        float xv[PER];
        if constexpr (PER == 8) {
            float4 v0 = *reinterpret_cast<const float4*>(xlp);
            float4 v1 = *reinterpret_cast<const float4*>(xlp + 4);
            xv[0] = v0.x; xv[1] = v0.y; xv[2] = v0.z; xv[3] = v0.w;
            xv[4] = v1.x; xv[5] = v1.y; xv[6] = v1.z; xv[7] = v1.w;
        } else {
            float2 v0 = *reinterpret_cast<const float2*>(xlp);
            xv[0] = v0.x; xv[1] = v0.y;
        }
        float s = 0.f;
        #pragma unroll
        for (int j = 0; j < PER; j++) {
            float t = xv[j] + xrv[j];
            t = (t > 0.f) ? t : 0.2f * t;
            s = fmaf(t, av[j], s);
        }
        // reduce within head group (G lanes, aligned segments)
        #pragma unroll
        for (int w = 1; w < G; w <<= 1) s += __shfl_xor_sync(0xffffffffu, s, w);

        float mn = fmaxf(m, s);
        float cold = __expf(m - mn);   // exp(-inf)=0 on first edge
        float wnew = __expf(s - mn);
        denom = denom * cold + wnew;
        #pragma unroll
        for (int j = 0; j < PER; j++) acc[j] = fmaf(acc[j], cold, wnew * xv[j]);
        m = mn;
    }
    float inv = 1.0f / denom;
    float ov[PER];
    const float* bp = bias + lane * PER;
    #pragma unroll
    for (int j = 0; j < PER; j++) {
        float o = acc[j] * inv + bp[j];
        if (do_relu) o = fmaxf(o, 0.f);
        ov[j] = o;
    }
    float* op = out + (size_t)node * F + lane * PER;
    if constexpr (PER == 8) {
        *reinterpret_cast<float4*>(op)     = make_float4(ov[0], ov[1], ov[2], ov[3]);
        *reinterpret_cast<float4*>(op + 4) = make_float4(ov[4], ov[5], ov[6], ov[7]);
    } else {
        *reinterpret_cast<float2*>(op) = make_float2(ov[0], ov[1]);
    }
}

// ---------------- fused VAE head: warp per node, weights in smem ----------------
__global__ __launch_bounds__(256) void vae_fused_kernel(
    const float* __restrict__ cs, const float* __restrict__ eps,
    const float* __restrict__ We1, const float* __restrict__ be1,
    const float* __restrict__ We2, const float* __restrict__ be2,
    const float* __restrict__ Wd1, const float* __restrict__ bd1,
    const float* __restrict__ Wd2, const float* __restrict__ bd2,
    float* __restrict__ out_z, float* __restrict__ out_mean,
    float* __restrict__ out_lv, float* __restrict__ out_rec, int n) {
    extern __shared__ float sm[];
    float* sWe1 = sm;            // 4096
    float* sWe2 = sm + 4096;     // 4096
    float* sWd1 = sm + 8192;     // 2048
    float* sWd2 = sm + 10240;    // 4096
    float* sb   = sm + 14336;    // 256 (be1,be2,bd1,bd2)
    float* buf  = sm + 14592;    // 8 warps * 64

    int tid = threadIdx.x;
    for (int i = tid; i < 4096; i += blockDim.x) {
        sWe1[i] = We1[i];
        sWe2[i] = We2[i];
        sWd2[i] = Wd2[i];
    }
    for (int i = tid; i < 2048; i += blockDim.x) sWd1[i] = Wd1[i];
    if (tid < 64) {
        sb[tid] = be1[tid];
        sb[64 + tid] = be2[tid];
        sb[128 + tid] = bd1[tid];
        sb[192 + tid] = bd2[tid];
    }
    __syncthreads();

    int wid = tid >> 5, lane = tid & 31;
    float* wb = buf + wid * 64;

    for (int node = blockIdx.x * 8 + wid; node < n; node += gridDim.x * 8) {
        wb[lane]      = cs[(size_t)node * 64 + lane];
        wb[lane + 32] = cs[(size_t)node * 64 + lane + 32];
        __syncwarp();
        // encoder layer 1 (64->64, relu)
        float a0 = sb[lane], a1 = sb[lane + 32];
        #pragma unroll
        for (int k = 0; k < 64; k++) {
            float xv = wb[k];
            a0 = fmaf(xv, sWe1[k * 64 + lane], a0);
            a1 = fmaf(xv, sWe1[k * 64 + lane + 32], a1);
        }
        a0 = fmaxf(a0, 0.f); a1 = fmaxf(a1, 0.f);
        __syncwarp();
        wb[lane] = a0; wb[lane + 32] = a1;
        __syncwarp();
        // encoder layer 2 (64->64): q0=mean[lane], q1=logvar[lane]
        float q0 = sb[64 + lane], q1 = sb[64 + lane + 32];
        #pragma unroll
        for (int k = 0; k < 64; k++) {
            float xv = wb[k];
            q0 = fmaf(xv, sWe2[k * 64 + lane], q0);
            q1 = fmaf(xv, sWe2[k * 64 + lane + 32], q1);
        }
        float stdv = __expf(0.5f * q1);
        float z = fmaf(stdv, eps[(size_t)node * 32 + lane], q0);
        out_z[(size_t)node * 32 + lane] = z;
        out_mean[(size_t)node * 32 + lane] = q0;
        out_lv[(size_t)node * 32 + lane] = q1;
        __syncwarp();
        wb[lane] = z;
        __syncwarp();
        // decoder layer 1 (32->64, relu)
        float d0 = sb[128 + lane], d1 = sb[128 + lane + 32];
        #pragma unroll
        for (int k = 0; k < 32; k++) {
            float xv = wb[k];
            d0 = fmaf(xv, sWd1[k * 64 + lane], d0);
            d1 = fmaf(xv, sWd1[k * 64 + lane + 32], d1);
        }
        d0 = fmaxf(d0, 0.f); d1 = fmaxf(d1, 0.f);
        __syncwarp();
        wb[lane] = d0; wb[lane + 32] = d1;
        __syncwarp();
        // decoder layer 2 (64->64)
        float r0 = sb[192 + lane], r1 = sb[192 + lane + 32];
        #pragma unroll
        for (int k = 0; k < 64; k++) {
            float xv = wb[k];
            r0 = fmaf(xv, sWd2[k * 64 + lane], r0);
            r1 = fmaf(xv, sWd2[k * 64 + lane + 32], r1);
        }
        out_rec[(size_t)node * 64 + lane] = r0;
        out_rec[(size_t)node * 64 + lane + 32] = r1;
        __syncwarp();
    }
}

// ---------------- host ----------------
extern "C" void kernel_launch(void* const* d_in, const int* in_sizes, int n_in,
                              void* d_out, int out_size) {
    const int n = NN, e = EE;
    const int*   ent_idx = (const int*)d_in[0];
    const float* ts      = (const float*)d_in[2];
    const int*   edge    = (const int*)d_in[3];
    const int*   tsidx   = (const int*)d_in[4];
    const float* eps     = (const float*)d_in[5];
    const float* etab    = (const float*)d_in[6];
    const float* ttab    = (const float*)d_in[7];
    const float* W1l = (const float*)d_in[8],  *b1l  = (const float*)d_in[9];
    const float* W1r = (const float*)d_in[10], *b1r  = (const float*)d_in[11];
    const float* a1  = (const float*)d_in[12], *bias1 = (const float*)d_in[13];
    const float* W2l = (const float*)d_in[14], *b2l  = (const float*)d_in[15];
    const float* W2r = (const float*)d_in[16], *b2r  = (const float*)d_in[17];
    const float* a2  = (const float*)d_in[18], *bias2 = (const float*)d_in[19];
    const float* We1 = (const float*)d_in[20], *be1  = (const float*)d_in[21];
    const float* We2 = (const float*)d_in[22], *be2  = (const float*)d_in[23];
    const float* Wd1 = (const float*)d_in[24], *bd1  = (const float*)d_in[25];
    const float* Wd2 = (const float*)d_in[26], *bd2  = (const float*)d_in[27];

    float* out = (float*)d_out;
    float* oz  = out;
    float* om  = out + (size_t)n * 32;
    float* ol  = out + (size_t)n * 64;
    float* orc = out + (size_t)n * 96;

    float *px, *pxl1, *pxr1, *ph, *pxl2, *pxr2, *pcs;
    int *pdeg, *poff, *pcur, *pcsr;
    cudaGetSymbolAddress((void**)&px, g_x);
    cudaGetSymbolAddress((void**)&pxl1, g_xl1);
    cudaGetSymbolAddress((void**)&pxr1, g_xr1);
    cudaGetSymbolAddress((void**)&ph, g_h);
    cudaGetSymbolAddress((void**)&pxl2, g_xl2);
    cudaGetSymbolAddress((void**)&pxr2, g_xr2);
    cudaGetSymbolAddress((void**)&pcs, g_cs);
    cudaGetSymbolAddress((void**)&pdeg, g_deg);
    cudaGetSymbolAddress((void**)&poff, g_off);
    cudaGetSymbolAddress((void**)&pcur, g_cur);
    cudaGetSymbolAddress((void**)&pcsr, g_csr);

    const int* esrc = edge;
    const int* edst = edge + e;

    // CSR build
    cudaMemsetAsync(pdeg, 0, n * sizeof(int));
    count_deg_kernel<<<(e + 255) / 256, 256>>>(edst, e, pdeg);
    scan_offsets_kernel<<<1, 1024>>>(pdeg, poff, pcur, n);
    scatter_kernel<<<(e + 255) / 256, 256>>>(esrc, edst, e, pcur, pcsr);

    // features
    gather_x_kernel<<<(n * 48 + 255) / 256, 256>>>(ts, ent_idx, tsidx, etab, ttab, px, n);

    // GAT layer 1
    dim3 g1(256 / 64, (n + 127) / 128);
    sgemm_bias_kernel<<<g1, 256>>>(px, W1l, b1l, pxl1, n, 256, 192);
    sgemm_bias_kernel<<<g1, 256>>>(px, W1r, b1r, pxr1, n, 256, 192);
    gat_aggregate<4, 64><<<(n + 7) / 8, 256>>>(pxl1, pxr1, a1, bias1, poff, pcsr, ph, n, 1);

    // GAT layer 2
    dim3 g2(1, (n + 127) / 128);
    sgemm_bias_kernel<<<g2, 256>>>(ph, W2l, b2l, pxl2, n, 64, 256);
    sgemm_bias_kernel<<<g2, 256>>>(ph, W2r, b2r, pxr2, n, 64, 256);
    gat_aggregate<1, 64><<<(n + 7) / 8, 256>>>(pxl2, pxr2, a2, bias2, poff, pcsr, pcs, n, 0);

    // VAE head
    cudaFuncSetAttribute(vae_fused_kernel, cudaFuncAttributeMaxDynamicSharedMemorySize, 61440);
    vae_fused_kernel<<<444, 256, 60416>>>(pcs, eps, We1, be1, We2, be2, Wd1, bd1, Wd2, bd2,
                                          oz, om, ol, orc, n);
}